// round 1
// baseline (speedup 1.0000x reference)
#include <cuda_runtime.h>
#include <cuda_bf16.h>
#include <math.h>

// Problem shape (fixed by reference):
//   B=8, N=2048, E=768
#define BATCH 8
#define SEQ   2048
#define EMB   768
#define ROWS  (BATCH * SEQ)          // 16384

// Scratch in __device__ globals (no allocations allowed).
__device__ float g_Q[ROWS * EMB];            // 50.3 MB
__device__ float g_K[ROWS * EMB];            // 50.3 MB
__device__ float g_V[ROWS * EMB];            // 50.3 MB
__device__ float g_S[BATCH * SEQ * SEQ];     // 134 MB
__device__ float g_O[ROWS * EMB];            // 50.3 MB

// ---------------------------------------------------------------------------
// Tiled SGEMM: C = alpha * A * op(B) (+ bias)
//   A: M x K row-major
//   TB=false: B is K x N row-major (NN)
//   TB=true : B is N x K row-major (NT, i.e. C = A * B^T)
// Tile: BM=BN=64, BK=16, 256 threads, 4x4 per-thread micro-tile.
// All dims must be multiples of tile sizes (true for this problem).
// blockIdx.z = batch index; sA/sB/sC are per-batch element strides.
// ---------------------------------------------------------------------------
#define BM 64
#define BN 64
#define BK 16

template<bool TB>
__global__ __launch_bounds__(256)
void gemm_tiled(const float* __restrict__ A, const float* __restrict__ B,
                const float* __restrict__ bias, float* __restrict__ C,
                int M, int N, int K,
                size_t sA, size_t sB, size_t sC, float alpha)
{
    A += (size_t)blockIdx.z * sA;
    B += (size_t)blockIdx.z * sB;
    C += (size_t)blockIdx.z * sC;

    __shared__ float As[BK][BM];        // As[k][m]
    __shared__ float Bs[BK][BN + 4];    // Bs[k][n], padded (stride 68 floats = 272B, 16B-aligned)

    const int tid = threadIdx.x;
    const int tx  = tid & 15;           // 0..15 -> n micro-tile
    const int ty  = tid >> 4;           // 0..15 -> m micro-tile
    const int m0  = blockIdx.y * BM;
    const int n0  = blockIdx.x * BN;

    // A-loader (also B-loader in TB mode): 64 rows x 16 cols, float4 per thread
    const int a_row = tid >> 2;         // 0..63
    const int a_col = (tid & 3) * 4;    // 0,4,8,12
    // B-loader (NN mode): 16 rows x 64 cols, float4 per thread
    const int b_row = tid >> 4;         // 0..15
    const int b_col = (tid & 15) * 4;   // 0..60

    float acc[4][4] = {};

    for (int k0 = 0; k0 < K; k0 += BK) {
        // ---- load A tile (transposed into As[k][m]) ----
        {
            float4 av = *(const float4*)&A[(size_t)(m0 + a_row) * K + k0 + a_col];
            As[a_col + 0][a_row] = av.x;
            As[a_col + 1][a_row] = av.y;
            As[a_col + 2][a_row] = av.z;
            As[a_col + 3][a_row] = av.w;
        }
        // ---- load B tile into Bs[k][n] ----
        if (!TB) {
            float4 bv = *(const float4*)&B[(size_t)(k0 + b_row) * N + n0 + b_col];
            *(float4*)&Bs[b_row][b_col] = bv;
        } else {
            float4 bv = *(const float4*)&B[(size_t)(n0 + a_row) * K + k0 + a_col];
            Bs[a_col + 0][a_row] = bv.x;
            Bs[a_col + 1][a_row] = bv.y;
            Bs[a_col + 2][a_row] = bv.z;
            Bs[a_col + 3][a_row] = bv.w;
        }
        __syncthreads();

        #pragma unroll
        for (int k = 0; k < BK; k++) {
            float4 a = *(const float4*)&As[k][ty * 4];
            float4 b = *(const float4*)&Bs[k][tx * 4];
            acc[0][0] += a.x * b.x; acc[0][1] += a.x * b.y; acc[0][2] += a.x * b.z; acc[0][3] += a.x * b.w;
            acc[1][0] += a.y * b.x; acc[1][1] += a.y * b.y; acc[1][2] += a.y * b.z; acc[1][3] += a.y * b.w;
            acc[2][0] += a.z * b.x; acc[2][1] += a.z * b.y; acc[2][2] += a.z * b.z; acc[2][3] += a.z * b.w;
            acc[3][0] += a.w * b.x; acc[3][1] += a.w * b.y; acc[3][2] += a.w * b.z; acc[3][3] += a.w * b.w;
        }
        __syncthreads();
    }

    // ---- epilogue ----
    float bj[4] = {0.f, 0.f, 0.f, 0.f};
    if (bias) {
        bj[0] = bias[n0 + tx * 4 + 0];
        bj[1] = bias[n0 + tx * 4 + 1];
        bj[2] = bias[n0 + tx * 4 + 2];
        bj[3] = bias[n0 + tx * 4 + 3];
    }
    #pragma unroll
    for (int i = 0; i < 4; i++) {
        float4 v;
        v.x = alpha * acc[i][0] + bj[0];
        v.y = alpha * acc[i][1] + bj[1];
        v.z = alpha * acc[i][2] + bj[2];
        v.w = alpha * acc[i][3] + bj[3];
        *(float4*)&C[(size_t)(m0 + ty * 4 + i) * N + n0 + tx * 4] = v;
    }
}

// ---------------------------------------------------------------------------
// Row softmax over S: 16384 rows of 2048. One block (256 thr) per row.
// Row kept in registers: 1 global read + 1 global write.
// ---------------------------------------------------------------------------
__global__ __launch_bounds__(256)
void softmax_rows(float* __restrict__ S)
{
    const int NC = SEQ;                  // 2048
    float* row = S + (size_t)blockIdx.x * NC;
    const int t = threadIdx.x;

    float v[8];
    float m = -1e30f;
    #pragma unroll
    for (int i = 0; i < 8; i++) {
        v[i] = row[t + i * 256];
        m = fmaxf(m, v[i]);
    }

    __shared__ float red[8];
    // warp-level max
    #pragma unroll
    for (int o = 16; o > 0; o >>= 1)
        m = fmaxf(m, __shfl_xor_sync(0xffffffffu, m, o));
    if ((t & 31) == 0) red[t >> 5] = m;
    __syncthreads();
    float mr = red[0];
    #pragma unroll
    for (int i = 1; i < 8; i++) mr = fmaxf(mr, red[i]);
    __syncthreads();

    float sum = 0.f;
    #pragma unroll
    for (int i = 0; i < 8; i++) {
        v[i] = __expf(v[i] - mr);
        sum += v[i];
    }
    #pragma unroll
    for (int o = 16; o > 0; o >>= 1)
        sum += __shfl_xor_sync(0xffffffffu, sum, o);
    if ((t & 31) == 0) red[t >> 5] = sum;
    __syncthreads();
    float sr = 0.f;
    #pragma unroll
    for (int i = 0; i < 8; i++) sr += red[i];
    float inv = 1.0f / sr;

    #pragma unroll
    for (int i = 0; i < 8; i++)
        row[t + i * 256] = v[i] * inv;
}

// ---------------------------------------------------------------------------
// Launch
// Inputs (metadata order): x, Wq, bq, Wk, bk, Wv, bv, Wo, bo
// Output: (8, 2048, 768) float32
// ---------------------------------------------------------------------------
extern "C" void kernel_launch(void* const* d_in, const int* in_sizes, int n_in,
                              void* d_out, int out_size)
{
    const float* x  = (const float*)d_in[0];
    const float* Wq = (const float*)d_in[1];
    const float* bq = (const float*)d_in[2];
    const float* Wk = (const float*)d_in[3];
    const float* bk = (const float*)d_in[4];
    const float* Wv = (const float*)d_in[5];
    const float* bv = (const float*)d_in[6];
    const float* Wo = (const float*)d_in[7];
    const float* bo = (const float*)d_in[8];
    float* out = (float*)d_out;

    float *pQ, *pK, *pV, *pS, *pO;
    cudaGetSymbolAddress((void**)&pQ, g_Q);
    cudaGetSymbolAddress((void**)&pK, g_K);
    cudaGetSymbolAddress((void**)&pV, g_V);
    cudaGetSymbolAddress((void**)&pS, g_S);
    cudaGetSymbolAddress((void**)&pO, g_O);

    const float scale = 1.0f / sqrtf((float)EMB);

    // 1) QKV projections: (16384x768) * (768x768) + bias
    {
        dim3 grid(EMB / BN, ROWS / BM, 1);
        gemm_tiled<false><<<grid, 256>>>(x, Wq, bq, pQ, ROWS, EMB, EMB, 0, 0, 0, 1.0f);
        gemm_tiled<false><<<grid, 256>>>(x, Wk, bk, pK, ROWS, EMB, EMB, 0, 0, 0, 1.0f);
        gemm_tiled<false><<<grid, 256>>>(x, Wv, bv, pV, ROWS, EMB, EMB, 0, 0, 0, 1.0f);
    }

    // 2) Scores: per batch S = scale * Q * K^T  (2048x768 x 768x2048)
    {
        dim3 grid(SEQ / BN, SEQ / BM, BATCH);
        gemm_tiled<true><<<grid, 256>>>(pQ, pK, nullptr, pS,
                                        SEQ, SEQ, EMB,
                                        (size_t)SEQ * EMB, (size_t)SEQ * EMB,
                                        (size_t)SEQ * SEQ, scale);
    }

    // 3) Row softmax over all 16384 rows
    softmax_rows<<<ROWS, 256>>>(pS);

    // 4) O = S * V  (2048x2048 x 2048x768, per batch)
    {
        dim3 grid(EMB / BN, SEQ / BM, BATCH);
        gemm_tiled<false><<<grid, 256>>>(pS, pV, nullptr, pO,
                                         SEQ, EMB, SEQ,
                                         (size_t)SEQ * SEQ, (size_t)SEQ * EMB,
                                         (size_t)SEQ * EMB, 1.0f);
    }

    // 5) Output projection: (16384x768) * (768x768) + bias -> d_out
    {
        dim3 grid(EMB / BN, ROWS / BM, 1);
        gemm_tiled<false><<<grid, 256>>>(pO, Wo, bo, out, ROWS, EMB, EMB, 0, 0, 0, 1.0f);
    }
}

// round 3
// speedup vs baseline: 1.3421x; 1.3421x over previous
#include <cuda_runtime.h>
#include <cuda_bf16.h>
#include <math.h>

// Problem shape (fixed by reference): B=8, N=2048, E=768
#define BATCH 8
#define SEQ   2048
#define EMB   768
#define ROWS  (BATCH * SEQ)          // 16384

// Scratch in __device__ globals (no allocations allowed).
__device__ float g_Q[ROWS * EMB];
__device__ float g_K[ROWS * EMB];
__device__ float g_V[ROWS * EMB];
__device__ float g_S[BATCH * SEQ * SEQ];
__device__ float g_O[ROWS * EMB];

// ---------------------------------------------------------------------------
// Split-bf16 tensor-core GEMM:  C = alpha * A * op(B) (+ bias)
//   fp32 inputs are split on-the-fly: v = hi + lo (both bf16), and
//   A*B ~= Ah*Bh + Ah*Bl + Al*Bh  (fp32 accumulate) -> ~16 mantissa bits.
// Tile: BM=BN=128, BK=16, 256 threads (8 warps, 4(m) x 2(n)), warp tile 32x64.
// mma.sync.aligned.m16n8k16.row.col.f32.bf16.bf16.f32
// All dims must be multiples of tile sizes (true here).
// ---------------------------------------------------------------------------
#define BM 128
#define BN 128
#define BK 16
#define LSTR 24   // smem row stride in bf16 elems (16 data + 8 pad = 48 bytes)

__device__ __forceinline__ void mma_bf16(float* c, const unsigned* a,
                                         unsigned b0, unsigned b1)
{
    asm volatile(
        "mma.sync.aligned.m16n8k16.row.col.f32.bf16.bf16.f32 "
        "{%0,%1,%2,%3}, {%4,%5,%6,%7}, {%8,%9}, {%0,%1,%2,%3};"
        : "+f"(c[0]), "+f"(c[1]), "+f"(c[2]), "+f"(c[3])
        : "r"(a[0]), "r"(a[1]), "r"(a[2]), "r"(a[3]), "r"(b0), "r"(b1));
}

__device__ __forceinline__ void split4(float4 v,
                                       __nv_bfloat16* H, __nv_bfloat16* L,
                                       int row, int col)
{
    __nv_bfloat16 hx = __float2bfloat16(v.x);
    __nv_bfloat16 hy = __float2bfloat16(v.y);
    __nv_bfloat16 hz = __float2bfloat16(v.z);
    __nv_bfloat16 hw = __float2bfloat16(v.w);
    __nv_bfloat162 h01; h01.x = hx; h01.y = hy;
    __nv_bfloat162 h23; h23.x = hz; h23.y = hw;
    __nv_bfloat162* ph = reinterpret_cast<__nv_bfloat162*>(&H[row * LSTR + col]);
    ph[0] = h01; ph[1] = h23;

    __nv_bfloat162 l01, l23;
    l01.x = __float2bfloat16(v.x - __bfloat162float(hx));
    l01.y = __float2bfloat16(v.y - __bfloat162float(hy));
    l23.x = __float2bfloat16(v.z - __bfloat162float(hz));
    l23.y = __float2bfloat16(v.w - __bfloat162float(hw));
    __nv_bfloat162* pl = reinterpret_cast<__nv_bfloat162*>(&L[row * LSTR + col]);
    pl[0] = l01; pl[1] = l23;
}

template<bool TB>
__global__ __launch_bounds__(256)
void gemm_bf16_split(const float* __restrict__ A, const float* __restrict__ B,
                     const float* __restrict__ bias, float* __restrict__ C,
                     int M, int N, int K,
                     size_t sA, size_t sB, size_t sC, float alpha)
{
    A += (size_t)blockIdx.z * sA;
    B += (size_t)blockIdx.z * sB;
    C += (size_t)blockIdx.z * sC;

    __shared__ __nv_bfloat16 Ah[BM * LSTR], Al[BM * LSTR];
    __shared__ __nv_bfloat16 Bh[BN * LSTR], Bl[BN * LSTR];

    const int tid  = threadIdx.x;
    const int lane = tid & 31;
    const int warp = tid >> 5;
    const int wm   = warp & 3;           // 0..3 -> m
    const int wn   = warp >> 2;          // 0..1 -> n
    const int g    = lane >> 2;          // 0..7
    const int t4   = lane & 3;           // 0..3
    const int m0   = blockIdx.y * BM;
    const int n0   = blockIdx.x * BN;

    // loader indices: 128 rows x 16 cols fp32 = 512 float4 / 256 thr = 2 each
    const int arow = tid >> 2;           // 0..63 (and +64)
    const int acol = (tid & 3) << 2;     // 0,4,8,12
    // NN B loader: 16 k-rows x 128 n
    const int bkr  = tid >> 5;           // 0..7 (and +8)
    const int bnc  = (tid & 31) << 2;    // 0..124

    float4 ra[2], rb[2];

    auto g_load = [&](int k0) {
        ra[0] = *(const float4*)&A[(size_t)(m0 + arow)      * K + k0 + acol];
        ra[1] = *(const float4*)&A[(size_t)(m0 + arow + 64) * K + k0 + acol];
        if constexpr (!TB) {
            rb[0] = *(const float4*)&B[(size_t)(k0 + bkr)     * N + n0 + bnc];
            rb[1] = *(const float4*)&B[(size_t)(k0 + bkr + 8) * N + n0 + bnc];
        } else {
            rb[0] = *(const float4*)&B[(size_t)(n0 + arow)      * K + k0 + acol];
            rb[1] = *(const float4*)&B[(size_t)(n0 + arow + 64) * K + k0 + acol];
        }
    };

    auto s_store = [&]() {
        split4(ra[0], Ah, Al, arow,      acol);
        split4(ra[1], Ah, Al, arow + 64, acol);
        if constexpr (!TB) {
            // scatter: rb[j] holds B[k][bnc..bnc+3] -> Bs[n][k]
            #pragma unroll
            for (int j = 0; j < 2; j++) {
                int k = bkr + 8 * j;
                float vv[4] = { rb[j].x, rb[j].y, rb[j].z, rb[j].w };
                #pragma unroll
                for (int i = 0; i < 4; i++) {
                    __nv_bfloat16 h = __float2bfloat16(vv[i]);
                    Bh[(bnc + i) * LSTR + k] = h;
                    Bl[(bnc + i) * LSTR + k] =
                        __float2bfloat16(vv[i] - __bfloat162float(h));
                }
            }
        } else {
            split4(rb[0], Bh, Bl, arow,      acol);
            split4(rb[1], Bh, Bl, arow + 64, acol);
        }
    };

    float acc[2][8][4] = {};

    g_load(0);
    s_store();
    __syncthreads();

    for (int k0 = BK; ; k0 += BK) {
        const bool more = (k0 < K);
        if (more) g_load(k0);   // global loads in flight during compute

        // A fragments (hi and lo) for both m-tiles
        unsigned afh[2][4], afl[2][4];
        #pragma unroll
        for (int mt = 0; mt < 2; mt++) {
            const int m = wm * 32 + mt * 16 + g;
            const __nv_bfloat16* p = &Ah[m * LSTR + 2 * t4];
            afh[mt][0] = *(const unsigned*)(p);
            afh[mt][1] = *(const unsigned*)(p + 8 * LSTR);
            afh[mt][2] = *(const unsigned*)(p + 8);
            afh[mt][3] = *(const unsigned*)(p + 8 * LSTR + 8);
            const __nv_bfloat16* q = &Al[m * LSTR + 2 * t4];
            afl[mt][0] = *(const unsigned*)(q);
            afl[mt][1] = *(const unsigned*)(q + 8 * LSTR);
            afl[mt][2] = *(const unsigned*)(q + 8);
            afl[mt][3] = *(const unsigned*)(q + 8 * LSTR + 8);
        }

        #pragma unroll
        for (int nt = 0; nt < 8; nt++) {
            const int n = wn * 64 + nt * 8 + g;
            const __nv_bfloat16* p = &Bh[n * LSTR + 2 * t4];
            unsigned bh0 = *(const unsigned*)(p);
            unsigned bh1 = *(const unsigned*)(p + 8);
            const __nv_bfloat16* q = &Bl[n * LSTR + 2 * t4];
            unsigned bl0 = *(const unsigned*)(q);
            unsigned bl1 = *(const unsigned*)(q + 8);
            #pragma unroll
            for (int mt = 0; mt < 2; mt++) {
                mma_bf16(acc[mt][nt], afh[mt], bh0, bh1);  // hi*hi
                mma_bf16(acc[mt][nt], afh[mt], bl0, bl1);  // hi*lo
                mma_bf16(acc[mt][nt], afl[mt], bh0, bh1);  // lo*hi
            }
        }

        if (!more) break;
        __syncthreads();
        s_store();
        __syncthreads();
    }

    // Epilogue: c0,c1 = (m, 2t),(m, 2t+1); c2,c3 = (m+8, ...)
    #pragma unroll
    for (int mt = 0; mt < 2; mt++) {
        #pragma unroll
        for (int nt = 0; nt < 8; nt++) {
            const int m = m0 + wm * 32 + mt * 16 + g;
            const int n = n0 + wn * 64 + nt * 8 + 2 * t4;
            float bx = 0.f, by = 0.f;
            if (bias) { bx = bias[n]; by = bias[n + 1]; }
            float2 v0, v1;
            v0.x = alpha * acc[mt][nt][0] + bx;
            v0.y = alpha * acc[mt][nt][1] + by;
            v1.x = alpha * acc[mt][nt][2] + bx;
            v1.y = alpha * acc[mt][nt][3] + by;
            *(float2*)&C[(size_t)m       * N + n] = v0;
            *(float2*)&C[(size_t)(m + 8) * N + n] = v1;
        }
    }
}

// ---------------------------------------------------------------------------
// Row softmax over S: 16384 rows of 2048. One block (256 thr) per row.
// ---------------------------------------------------------------------------
__global__ __launch_bounds__(256)
void softmax_rows(float* __restrict__ S)
{
    float* row = S + (size_t)blockIdx.x * SEQ;
    const int t = threadIdx.x;

    float v[8];
    float m = -1e30f;
    #pragma unroll
    for (int i = 0; i < 8; i++) {
        v[i] = row[t + i * 256];
        m = fmaxf(m, v[i]);
    }

    __shared__ float red[8];
    #pragma unroll
    for (int o = 16; o > 0; o >>= 1)
        m = fmaxf(m, __shfl_xor_sync(0xffffffffu, m, o));
    if ((t & 31) == 0) red[t >> 5] = m;
    __syncthreads();
    float mr = red[0];
    #pragma unroll
    for (int i = 1; i < 8; i++) mr = fmaxf(mr, red[i]);
    __syncthreads();

    float sum = 0.f;
    #pragma unroll
    for (int i = 0; i < 8; i++) {
        v[i] = __expf(v[i] - mr);
        sum += v[i];
    }
    #pragma unroll
    for (int o = 16; o > 0; o >>= 1)
        sum += __shfl_xor_sync(0xffffffffu, sum, o);
    if ((t & 31) == 0) red[t >> 5] = sum;
    __syncthreads();
    float sr = 0.f;
    #pragma unroll
    for (int i = 0; i < 8; i++) sr += red[i];
    float inv = 1.0f / sr;

    #pragma unroll
    for (int i = 0; i < 8; i++)
        row[t + i * 256] = v[i] * inv;
}

// ---------------------------------------------------------------------------
// Launch.  Inputs: x, Wq, bq, Wk, bk, Wv, bv, Wo, bo.  Output fp32 (8,2048,768)
// ---------------------------------------------------------------------------
extern "C" void kernel_launch(void* const* d_in, const int* in_sizes, int n_in,
                              void* d_out, int out_size)
{
    const float* x  = (const float*)d_in[0];
    const float* Wq = (const float*)d_in[1];
    const float* bq = (const float*)d_in[2];
    const float* Wk = (const float*)d_in[3];
    const float* bk = (const float*)d_in[4];
    const float* Wv = (const float*)d_in[5];
    const float* bv = (const float*)d_in[6];
    const float* Wo = (const float*)d_in[7];
    const float* bo = (const float*)d_in[8];
    float* out = (float*)d_out;

    float *pQ, *pK, *pV, *pS, *pO;
    cudaGetSymbolAddress((void**)&pQ, g_Q);
    cudaGetSymbolAddress((void**)&pK, g_K);
    cudaGetSymbolAddress((void**)&pV, g_V);
    cudaGetSymbolAddress((void**)&pS, g_S);
    cudaGetSymbolAddress((void**)&pO, g_O);

    const float scale = 1.0f / sqrtf((float)EMB);

    // 1) QKV projections: (16384x768) * (768x768) + bias   (NN)
    {
        dim3 grid(EMB / BN, ROWS / BM, 1);
        gemm_bf16_split<false><<<grid, 256>>>(x, Wq, bq, pQ, ROWS, EMB, EMB, 0, 0, 0, 1.0f);
        gemm_bf16_split<false><<<grid, 256>>>(x, Wk, bk, pK, ROWS, EMB, EMB, 0, 0, 0, 1.0f);
        gemm_bf16_split<false><<<grid, 256>>>(x, Wv, bv, pV, ROWS, EMB, EMB, 0, 0, 0, 1.0f);
    }

    // 2) Scores: per batch S = scale * Q * K^T   (NT)
    {
        dim3 grid(SEQ / BN, SEQ / BM, BATCH);
        gemm_bf16_split<true><<<grid, 256>>>(pQ, pK, nullptr, pS,
                                             SEQ, SEQ, EMB,
                                             (size_t)SEQ * EMB, (size_t)SEQ * EMB,
                                             (size_t)SEQ * SEQ, scale);
    }

    // 3) Row softmax
    softmax_rows<<<ROWS, 256>>>(pS);

    // 4) O = S * V   (NN, per batch)
    {
        dim3 grid(EMB / BN, SEQ / BM, BATCH);
        gemm_bf16_split<false><<<grid, 256>>>(pS, pV, nullptr, pO,
                                              SEQ, EMB, SEQ,
                                              (size_t)SEQ * SEQ, (size_t)SEQ * EMB,
                                              (size_t)SEQ * EMB, 1.0f);
    }

    // 5) Output projection -> d_out   (NN)
    {
        dim3 grid(EMB / BN, ROWS / BM, 1);
        gemm_bf16_split<false><<<grid, 256>>>(pO, Wo, bo, out, ROWS, EMB, EMB, 0, 0, 0, 1.0f);
    }
}

// round 7
// speedup vs baseline: 2.1156x; 1.5764x over previous
#include <cuda_runtime.h>
#include <cuda_bf16.h>
#include <math.h>
#include <stdint.h>

// Problem shape (fixed by reference): B=8, N=2048, E=768
#define BATCH 8
#define SEQ   2048
#define EMB   768
#define ROWS  (BATCH * SEQ)          // 16384

// ---------------------------------------------------------------------------
// Scratch (__device__ globals; no allocations allowed).
// All GEMM operands live as split bf16 (hi, lo) pairs, k-contiguous.
// ---------------------------------------------------------------------------
__device__ __align__(256) __nv_bfloat16 g_xh[ROWS * EMB], g_xl[ROWS * EMB];
__device__ __align__(256) __nv_bfloat16 g_Wqh[EMB * EMB], g_Wql[EMB * EMB];
__device__ __align__(256) __nv_bfloat16 g_Wkh[EMB * EMB], g_Wkl[EMB * EMB];
__device__ __align__(256) __nv_bfloat16 g_Wvh[EMB * EMB], g_Wvl[EMB * EMB];
__device__ __align__(256) __nv_bfloat16 g_Woh[EMB * EMB], g_Wol[EMB * EMB];
__device__ __align__(256) __nv_bfloat16 g_Qh[ROWS * EMB], g_Ql[ROWS * EMB];
__device__ __align__(256) __nv_bfloat16 g_Kh[ROWS * EMB], g_Kl[ROWS * EMB];
__device__ __align__(256) float         g_V [ROWS * EMB];
__device__ __align__(256) __nv_bfloat16 g_Vth[ROWS * EMB], g_Vtl[ROWS * EMB]; // [b][e][s]
__device__ __align__(256) __nv_bfloat16 g_Sh[(size_t)BATCH * SEQ * SEQ];
__device__ __align__(256) __nv_bfloat16 g_Sl[(size_t)BATCH * SEQ * SEQ];
__device__ __align__(256) __nv_bfloat16 g_Oh[ROWS * EMB], g_Ol[ROWS * EMB];

// ---------------------------------------------------------------------------
// Helpers
// ---------------------------------------------------------------------------
__device__ __forceinline__ uint32_t smem_u32(const void* p) {
    uint32_t a;
    asm("{ .reg .u64 t; cvta.to.shared.u64 t, %1; cvt.u32.u64 %0, t; }"
        : "=r"(a) : "l"(p));
    return a;
}

__device__ __forceinline__ void ldsm4(uint32_t* r, uint32_t addr) {
    asm volatile("ldmatrix.sync.aligned.m8n8.x4.shared.b16 {%0,%1,%2,%3}, [%4];"
                 : "=r"(r[0]), "=r"(r[1]), "=r"(r[2]), "=r"(r[3]) : "r"(addr));
}

__device__ __forceinline__ void mma_bf16(float* c, const uint32_t* a,
                                         uint32_t b0, uint32_t b1)
{
    asm volatile(
        "mma.sync.aligned.m16n8k16.row.col.f32.bf16.bf16.f32 "
        "{%0,%1,%2,%3}, {%4,%5,%6,%7}, {%8,%9}, {%0,%1,%2,%3};"
        : "+f"(c[0]), "+f"(c[1]), "+f"(c[2]), "+f"(c[3])
        : "r"(a[0]), "r"(a[1]), "r"(a[2]), "r"(a[3]), "r"(b0), "r"(b1));
}

#define CP_ASYNC16(dst, src) \
    asm volatile("cp.async.cg.shared.global [%0], [%1], 16;" :: "r"(dst), "l"(src))
#define CP_COMMIT() asm volatile("cp.async.commit_group;" ::: "memory")
#define CP_WAIT1()  asm volatile("cp.async.wait_group 1;"  ::: "memory")

__device__ __forceinline__ void split_store2(__nv_bfloat16* Ch, __nv_bfloat16* Cl,
                                             size_t idx, float v0, float v1)
{
    __nv_bfloat162 h = __floats2bfloat162_rn(v0, v1);
    float2 hf = __bfloat1622float2(h);
    __nv_bfloat162 l = __floats2bfloat162_rn(v0 - hf.x, v1 - hf.y);
    *(__nv_bfloat162*)(Ch + idx) = h;
    *(__nv_bfloat162*)(Cl + idx) = l;
}

// ---------------------------------------------------------------------------
// HMMA split-bf16 GEMM.
//   C[M,N] = alpha * A * B^T (+ bias), A:[M,K] k-contig (hi,lo), B:[N,K] k-contig.
//   3-term: Ah*Bh + Ah*Bl + Al*Bh, fp32 accumulate.
// Block tile 128x128, BK=32, 3-stage cp.async pipeline, 256 thr (2m x 4n warps,
// warp tile 64x32). OUT=0: split bf16 pair out; OUT=1: fp32 out.
// Smem/stage: A 16KB + B 16KB; rows of 128B = {k16 hi | k16 lo} x2, XOR swizzle.
// ---------------------------------------------------------------------------
#define STAGE_BYTES 32768
#define GEMM_SMEM  (3 * STAGE_BYTES)

template<int OUT>
__global__ void __launch_bounds__(256, 2)
gemm_hmma(const __nv_bfloat16* __restrict__ Ah, const __nv_bfloat16* __restrict__ Al,
          int lda, size_t bsA,
          const __nv_bfloat16* __restrict__ Bh, const __nv_bfloat16* __restrict__ Bl,
          int ldb, size_t bsB,
          void* __restrict__ Coh, void* __restrict__ Col,
          int ldc, size_t bsC,
          const float* __restrict__ bias, float alpha, int K)
{
    extern __shared__ char smem[];
    const uint32_t sbase = smem_u32(smem);

    Ah += (size_t)blockIdx.z * bsA;  Al += (size_t)blockIdx.z * bsA;
    Bh += (size_t)blockIdx.z * bsB;  Bl += (size_t)blockIdx.z * bsB;

    const int tid  = threadIdx.x;
    const int lane = tid & 31;
    const int warp = tid >> 5;
    const int wm   = warp & 1;            // 2 warps in m
    const int wn   = warp >> 1;           // 4 warps in n
    const int m0   = blockIdx.y * 128;
    const int n0   = blockIdx.x * 128;

    // ---- loader precompute: thread -> (row, 4 chunks). chunk c(0..7):
    //      kk=c>>2 (k16 half), hl=(c>>1)&1 (hi/lo), half=c&1 (8-elem half)
    const int lrow = tid >> 1;
    const int lgrp = tid & 1;
    const __nv_bfloat16* asrc[4];
    const __nv_bfloat16* bsrc[4];
    uint32_t adst[4], bdst[4];
    #pragma unroll
    for (int j = 0; j < 4; j++) {
        const int c    = lgrp * 4 + j;
        const int kk   = c >> 2, hl = (c >> 1) & 1, half = c & 1;
        const int koff = kk * 16 + half * 8;
        asrc[j] = (hl ? Al : Ah) + (size_t)(m0 + lrow) * lda + koff;
        bsrc[j] = (hl ? Bl : Bh) + (size_t)(n0 + lrow) * ldb + koff;
        const uint32_t off = (uint32_t)lrow * 128 + (uint32_t)((c ^ (lrow & 7)) << 4);
        adst[j] = off;
        bdst[j] = 16384u + off;
    }

    auto load_stage = [&](int s, int kt) {
        const uint32_t st = sbase + (uint32_t)s * STAGE_BYTES;
        const int ke = kt * 32;
        #pragma unroll
        for (int j = 0; j < 4; j++) {
            CP_ASYNC16(st + adst[j], asrc[j] + ke);
            CP_ASYNC16(st + bdst[j], bsrc[j] + ke);
        }
    };

    // ---- ldmatrix address precompute
    const int g  = lane >> 3;
    const int r8 = lane & 7;
    uint32_t a_ro[4]; int a_sw[4];
    #pragma unroll
    for (int mf = 0; mf < 4; mf++) {
        const int row = wm * 64 + mf * 16 + ((g & 1) << 3) + r8;
        a_ro[mf] = (uint32_t)row * 128;
        a_sw[mf] = row & 7;
    }
    const int a_ch = g >> 1;
    uint32_t b_ro[2]; int b_sw[2];
    #pragma unroll
    for (int nf = 0; nf < 2; nf++) {
        const int row = wn * 32 + nf * 16 + ((g >> 1) << 3) + r8;
        b_ro[nf] = 16384u + (uint32_t)row * 128;
        b_sw[nf] = row & 7;
    }
    const int b_ch = g & 1;

    float acc[4][4][4];
    #pragma unroll
    for (int i = 0; i < 4; i++)
        #pragma unroll
        for (int j = 0; j < 4; j++)
            #pragma unroll
            for (int k = 0; k < 4; k++) acc[i][j][k] = 0.f;

    const int nK = K / 32;                // >= 24 always
    load_stage(0, 0); CP_COMMIT();
    load_stage(1, 1); CP_COMMIT();

    for (int kt = 0; kt < nK; kt++) {
        const int s = kt % 3;
        CP_WAIT1();
        __syncthreads();
        if (kt + 2 < nK) load_stage((kt + 2) % 3, kt + 2);
        CP_COMMIT();

        const uint32_t sa = sbase + (uint32_t)s * STAGE_BYTES;
        #pragma unroll
        for (int kkk = 0; kkk < 2; kkk++) {
            uint32_t ahf[4][4], alf[4][4], bhf[2][4], blf[2][4];
            #pragma unroll
            for (int mf = 0; mf < 4; mf++) {
                const int ch = (kkk << 2) | (0 << 1) | a_ch;
                const int cl = (kkk << 2) | (1 << 1) | a_ch;
                ldsm4(ahf[mf], sa + a_ro[mf] + (uint32_t)((ch ^ a_sw[mf]) << 4));
                ldsm4(alf[mf], sa + a_ro[mf] + (uint32_t)((cl ^ a_sw[mf]) << 4));
            }
            #pragma unroll
            for (int nf = 0; nf < 2; nf++) {
                const int ch = (kkk << 2) | (0 << 1) | b_ch;
                const int cl = (kkk << 2) | (1 << 1) | b_ch;
                ldsm4(bhf[nf], sa + b_ro[nf] + (uint32_t)((ch ^ b_sw[nf]) << 4));
                ldsm4(blf[nf], sa + b_ro[nf] + (uint32_t)((cl ^ b_sw[nf]) << 4));
            }
            #pragma unroll
            for (int mf = 0; mf < 4; mf++) {
                #pragma unroll
                for (int nf = 0; nf < 4; nf++) {
                    const uint32_t* bh = &bhf[nf >> 1][(nf & 1) * 2];
                    const uint32_t* bl = &blf[nf >> 1][(nf & 1) * 2];
                    mma_bf16(acc[mf][nf], ahf[mf], bh[0], bh[1]);  // hi*hi
                    mma_bf16(acc[mf][nf], ahf[mf], bl[0], bl[1]);  // hi*lo
                    mma_bf16(acc[mf][nf], alf[mf], bh[0], bh[1]);  // lo*hi
                }
            }
        }
        // next iter's top __syncthreads protects stage reuse
    }

    // ---- epilogue
    const int mr = lane >> 2;
    const int nc = (lane & 3) * 2;
    #pragma unroll
    for (int mf = 0; mf < 4; mf++) {
        #pragma unroll
        for (int nf = 0; nf < 4; nf++) {
            const int m = m0 + wm * 64 + mf * 16 + mr;
            const int n = n0 + wn * 32 + nf * 8 + nc;
            float b0 = 0.f, b1 = 0.f;
            if (bias) { b0 = bias[n]; b1 = bias[n + 1]; }
            const float v0 = alpha * acc[mf][nf][0] + b0;
            const float v1 = alpha * acc[mf][nf][1] + b1;
            const float v2 = alpha * acc[mf][nf][2] + b0;
            const float v3 = alpha * acc[mf][nf][3] + b1;
            if (OUT == 1) {
                float* C = (float*)Coh + (size_t)blockIdx.z * bsC;
                *(float2*)&C[(size_t)m * ldc + n]       = make_float2(v0, v1);
                *(float2*)&C[(size_t)(m + 8) * ldc + n] = make_float2(v2, v3);
            } else {
                __nv_bfloat16* Ch = (__nv_bfloat16*)Coh + (size_t)blockIdx.z * bsC;
                __nv_bfloat16* Cl = (__nv_bfloat16*)Col + (size_t)blockIdx.z * bsC;
                split_store2(Ch, Cl, (size_t)m * ldc + n, v0, v1);
                split_store2(Ch, Cl, (size_t)(m + 8) * ldc + n, v2, v3);
            }
        }
    }
}

// ---------------------------------------------------------------------------
// Elementwise fp32 -> (hi, lo) bf16 split.
// ---------------------------------------------------------------------------
__global__ void __launch_bounds__(256)
split_f32(const float4* __restrict__ in, __nv_bfloat162* __restrict__ oh,
          __nv_bfloat162* __restrict__ ol, int n4)
{
    const int i = blockIdx.x * 256 + threadIdx.x;
    if (i >= n4) return;
    const float4 v = in[i];
    __nv_bfloat162 h01 = __floats2bfloat162_rn(v.x, v.y);
    __nv_bfloat162 h23 = __floats2bfloat162_rn(v.z, v.w);
    float2 f01 = __bfloat1622float2(h01);
    float2 f23 = __bfloat1622float2(h23);
    oh[2 * i]     = h01;
    oh[2 * i + 1] = h23;
    ol[2 * i]     = __floats2bfloat162_rn(v.x - f01.x, v.y - f01.y);
    ol[2 * i + 1] = __floats2bfloat162_rn(v.z - f23.x, v.w - f23.y);
}

// ---------------------------------------------------------------------------
// Transpose + split: in fp32 [R][C] (batch stride bsIn) -> out bf16 hi/lo [C][R].
// Block (32,8), 32x32 tiles.
// ---------------------------------------------------------------------------
__global__ void __launch_bounds__(256)
transpose_split(const float* __restrict__ in,
                __nv_bfloat16* __restrict__ oh, __nv_bfloat16* __restrict__ ol,
                int R, int C, size_t bsIn, size_t bsOut)
{
    __shared__ float tile[32][33];
    in += (size_t)blockIdx.z * bsIn;
    oh += (size_t)blockIdx.z * bsOut;
    ol += (size_t)blockIdx.z * bsOut;

    const int tx = threadIdx.x, ty = threadIdx.y;
    const int x  = blockIdx.x * 32 + tx;       // col in input
    const int y0 = blockIdx.y * 32;
    #pragma unroll
    for (int j = 0; j < 4; j++)
        tile[ty + j * 8][tx] = in[(size_t)(y0 + ty + j * 8) * C + x];
    __syncthreads();
    #pragma unroll
    for (int j = 0; j < 4; j++) {
        const float v = tile[tx][ty + j * 8];  // = in[y0+tx][bx*32+ty+j*8]
        const __nv_bfloat16 h = __float2bfloat16(v);
        const __nv_bfloat16 l = __float2bfloat16(v - __bfloat162float(h));
        const size_t o = (size_t)(blockIdx.x * 32 + ty + j * 8) * R + y0 + tx;
        oh[o] = h;
        ol[o] = l;
    }
}

// ---------------------------------------------------------------------------
// Softmax over split-bf16 rows (in place): reconstruct hi+lo, softmax fp32,
// write back split. 16384 rows of 2048; 1 block (256 thr) per row.
// ---------------------------------------------------------------------------
__global__ void __launch_bounds__(256)
softmax_split(__nv_bfloat16* __restrict__ Sh, __nv_bfloat16* __restrict__ Sl)
{
    const size_t base = (size_t)blockIdx.x * SEQ;
    __nv_bfloat162* ph = (__nv_bfloat162*)(Sh + base);
    __nv_bfloat162* pl = (__nv_bfloat162*)(Sl + base);
    const int t = threadIdx.x;

    float v[8];
    float m = -1e30f;
    #pragma unroll
    for (int i = 0; i < 4; i++) {
        const float2 hf = __bfloat1622float2(ph[t + i * 256]);
        const float2 lf = __bfloat1622float2(pl[t + i * 256]);
        v[2 * i]     = hf.x + lf.x;
        v[2 * i + 1] = hf.y + lf.y;
        m = fmaxf(m, fmaxf(v[2 * i], v[2 * i + 1]));
    }

    __shared__ float red[8];
    #pragma unroll
    for (int o = 16; o > 0; o >>= 1)
        m = fmaxf(m, __shfl_xor_sync(0xffffffffu, m, o));
    if ((t & 31) == 0) red[t >> 5] = m;
    __syncthreads();
    float mr = red[0];
    #pragma unroll
    for (int i = 1; i < 8; i++) mr = fmaxf(mr, red[i]);
    __syncthreads();

    float sum = 0.f;
    #pragma unroll
    for (int i = 0; i < 8; i++) {
        v[i] = __expf(v[i] - mr);
        sum += v[i];
    }
    #pragma unroll
    for (int o = 16; o > 0; o >>= 1)
        sum += __shfl_xor_sync(0xffffffffu, sum, o);
    if ((t & 31) == 0) red[t >> 5] = sum;
    __syncthreads();
    float sr = 0.f;
    #pragma unroll
    for (int i = 0; i < 8; i++) sr += red[i];
    const float inv = 1.0f / sr;

    #pragma unroll
    for (int i = 0; i < 4; i++) {
        const float p0 = v[2 * i] * inv;
        const float p1 = v[2 * i + 1] * inv;
        const __nv_bfloat162 h = __floats2bfloat162_rn(p0, p1);
        const float2 hf = __bfloat1622float2(h);
        ph[t + i * 256] = h;
        pl[t + i * 256] = __floats2bfloat162_rn(p0 - hf.x, p1 - hf.y);
    }
}

// ---------------------------------------------------------------------------
// Launch.  Inputs: x, Wq, bq, Wk, bk, Wv, bv, Wo, bo.  Output fp32 (8,2048,768)
// ---------------------------------------------------------------------------
extern "C" void kernel_launch(void* const* d_in, const int* in_sizes, int n_in,
                              void* d_out, int out_size)
{
    const float* x  = (const float*)d_in[0];
    const float* Wq = (const float*)d_in[1];
    const float* bq = (const float*)d_in[2];
    const float* Wk = (const float*)d_in[3];
    const float* bk = (const float*)d_in[4];
    const float* Wv = (const float*)d_in[5];
    const float* bv = (const float*)d_in[6];
    const float* Wo = (const float*)d_in[7];
    const float* bo = (const float*)d_in[8];
    float* out = (float*)d_out;

    __nv_bfloat16 *xh, *xl, *Wqh, *Wql, *Wkh, *Wkl, *Wvh, *Wvl, *Woh, *Wol;
    __nv_bfloat16 *Qh, *Ql, *Kh, *Kl, *Vth, *Vtl, *Sh, *Sl, *Oh, *Ol;
    float* V;
    cudaGetSymbolAddress((void**)&xh,  g_xh);  cudaGetSymbolAddress((void**)&xl,  g_xl);
    cudaGetSymbolAddress((void**)&Wqh, g_Wqh); cudaGetSymbolAddress((void**)&Wql, g_Wql);
    cudaGetSymbolAddress((void**)&Wkh, g_Wkh); cudaGetSymbolAddress((void**)&Wkl, g_Wkl);
    cudaGetSymbolAddress((void**)&Wvh, g_Wvh); cudaGetSymbolAddress((void**)&Wvl, g_Wvl);
    cudaGetSymbolAddress((void**)&Woh, g_Woh); cudaGetSymbolAddress((void**)&Wol, g_Wol);
    cudaGetSymbolAddress((void**)&Qh,  g_Qh);  cudaGetSymbolAddress((void**)&Ql,  g_Ql);
    cudaGetSymbolAddress((void**)&Kh,  g_Kh);  cudaGetSymbolAddress((void**)&Kl,  g_Kl);
    cudaGetSymbolAddress((void**)&V,   g_V);
    cudaGetSymbolAddress((void**)&Vth, g_Vth); cudaGetSymbolAddress((void**)&Vtl, g_Vtl);
    cudaGetSymbolAddress((void**)&Sh,  g_Sh);  cudaGetSymbolAddress((void**)&Sl,  g_Sl);
    cudaGetSymbolAddress((void**)&Oh,  g_Oh);  cudaGetSymbolAddress((void**)&Ol,  g_Ol);

    cudaFuncSetAttribute(gemm_hmma<0>, cudaFuncAttributeMaxDynamicSharedMemorySize, GEMM_SMEM);
    cudaFuncSetAttribute(gemm_hmma<1>, cudaFuncAttributeMaxDynamicSharedMemorySize, GEMM_SMEM);

    const float scale = 1.0f / sqrtf((float)EMB);
    const dim3 tb(32, 8);

    // 0) split x; transpose+split weights (W[e][f] -> Wt[f][e])
    split_f32<<<(ROWS * EMB / 4 + 255) / 256, 256>>>(
        (const float4*)x, (__nv_bfloat162*)xh, (__nv_bfloat162*)xl, ROWS * EMB / 4);
    {
        dim3 g(EMB / 32, EMB / 32, 1);
        transpose_split<<<g, tb>>>(Wq, Wqh, Wql, EMB, EMB, 0, 0);
        transpose_split<<<g, tb>>>(Wk, Wkh, Wkl, EMB, EMB, 0, 0);
        transpose_split<<<g, tb>>>(Wv, Wvh, Wvl, EMB, EMB, 0, 0);
        transpose_split<<<g, tb>>>(Wo, Woh, Wol, EMB, EMB, 0, 0);
    }

    // 1) QKV projections (M=16384, N=768, K=768). Q,K -> split; V -> fp32.
    {
        dim3 g(EMB / 128, ROWS / 128, 1);
        gemm_hmma<0><<<g, 256, GEMM_SMEM>>>(xh, xl, EMB, 0, Wqh, Wql, EMB, 0,
                                            Qh, Ql, EMB, 0, bq, 1.0f, EMB);
        gemm_hmma<0><<<g, 256, GEMM_SMEM>>>(xh, xl, EMB, 0, Wkh, Wkl, EMB, 0,
                                            Kh, Kl, EMB, 0, bk, 1.0f, EMB);
        gemm_hmma<1><<<g, 256, GEMM_SMEM>>>(xh, xl, EMB, 0, Wvh, Wvl, EMB, 0,
                                            V, nullptr, EMB, 0, bv, 1.0f, EMB);
    }

    // 2) V transpose+split per batch: [s][e] -> [e][s]
    {
        dim3 g(EMB / 32, SEQ / 32, BATCH);
        transpose_split<<<g, tb>>>(V, Vth, Vtl, SEQ, EMB,
                                   (size_t)SEQ * EMB, (size_t)SEQ * EMB);
    }

    // 3) Scores: S = scale * Q * K^T per batch -> split bf16
    {
        dim3 g(SEQ / 128, SEQ / 128, BATCH);
        gemm_hmma<0><<<g, 256, GEMM_SMEM>>>(Qh, Ql, EMB, (size_t)SEQ * EMB,
                                            Kh, Kl, EMB, (size_t)SEQ * EMB,
                                            Sh, Sl, SEQ, (size_t)SEQ * SEQ,
                                            nullptr, scale, EMB);
    }

    // 4) Softmax (in place on split S)
    softmax_split<<<ROWS, 256>>>(Sh, Sl);

    // 5) O = P * V per batch (A = S [q][s], B = Vt [e][s]) -> split bf16
    {
        dim3 g(EMB / 128, SEQ / 128, BATCH);
        gemm_hmma<0><<<g, 256, GEMM_SMEM>>>(Sh, Sl, SEQ, (size_t)SEQ * SEQ,
                                            Vth, Vtl, SEQ, (size_t)EMB * SEQ,
                                            Oh, Ol, EMB, (size_t)SEQ * EMB,
                                            nullptr, 1.0f, SEQ);
    }

    // 6) Output projection -> d_out (fp32)
    {
        dim3 g(EMB / 128, ROWS / 128, 1);
        gemm_hmma<1><<<g, 256, GEMM_SMEM>>>(Oh, Ol, EMB, 0, Woh, Wol, EMB, 0,
                                            out, nullptr, EMB, 0, bo, 1.0f, EMB);
    }
}

// round 8
// speedup vs baseline: 2.3797x; 1.1249x over previous
#include <cuda_runtime.h>
#include <cuda_bf16.h>
#include <math.h>
#include <stdint.h>

// Problem shape (fixed by reference): B=8, N=2048, E=768
#define BATCH 8
#define SEQ   2048
#define EMB   768
#define ROWS  (BATCH * SEQ)          // 16384

// ---------------------------------------------------------------------------
// Scratch (__device__ globals; no allocations allowed).
// All GEMM operands live as split bf16 (hi, lo) pairs, k-contiguous.
// ---------------------------------------------------------------------------
__device__ __align__(256) __nv_bfloat16 g_xh[ROWS * EMB], g_xl[ROWS * EMB];
__device__ __align__(256) __nv_bfloat16 g_Wqh[EMB * EMB], g_Wql[EMB * EMB];
__device__ __align__(256) __nv_bfloat16 g_Wkh[EMB * EMB], g_Wkl[EMB * EMB];
__device__ __align__(256) __nv_bfloat16 g_Wvh[EMB * EMB], g_Wvl[EMB * EMB];
__device__ __align__(256) __nv_bfloat16 g_Woh[EMB * EMB], g_Wol[EMB * EMB];
__device__ __align__(256) __nv_bfloat16 g_Qh[ROWS * EMB], g_Ql[ROWS * EMB];
__device__ __align__(256) __nv_bfloat16 g_Kh[ROWS * EMB], g_Kl[ROWS * EMB];
__device__ __align__(256) float         g_V [ROWS * EMB];
__device__ __align__(256) __nv_bfloat16 g_Vth[ROWS * EMB], g_Vtl[ROWS * EMB]; // [b][e][s]
__device__ __align__(256) __nv_bfloat16 g_Sh[(size_t)BATCH * SEQ * SEQ];
__device__ __align__(256) __nv_bfloat16 g_Sl[(size_t)BATCH * SEQ * SEQ];
__device__ __align__(256) __nv_bfloat16 g_Oh[ROWS * EMB], g_Ol[ROWS * EMB];

// ---------------------------------------------------------------------------
// Helpers
// ---------------------------------------------------------------------------
__device__ __forceinline__ uint32_t smem_u32(const void* p) {
    uint32_t a;
    asm("{ .reg .u64 t; cvta.to.shared.u64 t, %1; cvt.u32.u64 %0, t; }"
        : "=r"(a) : "l"(p));
    return a;
}

__device__ __forceinline__ void ldsm4(uint32_t* r, uint32_t addr) {
    asm volatile("ldmatrix.sync.aligned.m8n8.x4.shared.b16 {%0,%1,%2,%3}, [%4];"
                 : "=r"(r[0]), "=r"(r[1]), "=r"(r[2]), "=r"(r[3]) : "r"(addr));
}

__device__ __forceinline__ void mma_bf16(float* c, const uint32_t* a,
                                         uint32_t b0, uint32_t b1)
{
    asm volatile(
        "mma.sync.aligned.m16n8k16.row.col.f32.bf16.bf16.f32 "
        "{%0,%1,%2,%3}, {%4,%5,%6,%7}, {%8,%9}, {%0,%1,%2,%3};"
        : "+f"(c[0]), "+f"(c[1]), "+f"(c[2]), "+f"(c[3])
        : "r"(a[0]), "r"(a[1]), "r"(a[2]), "r"(a[3]), "r"(b0), "r"(b1));
}

#define CP_ASYNC16(dst, src) \
    asm volatile("cp.async.cg.shared.global [%0], [%1], 16;" :: "r"(dst), "l"(src))
#define CP_COMMIT() asm volatile("cp.async.commit_group;" ::: "memory")
#define CP_WAIT1()  asm volatile("cp.async.wait_group 1;"  ::: "memory")

__device__ __forceinline__ void split_store2(__nv_bfloat16* Ch, __nv_bfloat16* Cl,
                                             size_t idx, float v0, float v1)
{
    __nv_bfloat162 h = __floats2bfloat162_rn(v0, v1);
    float2 hf = __bfloat1622float2(h);
    __nv_bfloat162 l = __floats2bfloat162_rn(v0 - hf.x, v1 - hf.y);
    *(__nv_bfloat162*)(Ch + idx) = h;
    *(__nv_bfloat162*)(Cl + idx) = l;
}

// ---------------------------------------------------------------------------
// HMMA split-bf16 GEMM.
//   C[M,N] = alpha * A * B^T (+ bias), A:[M,K] k-contig (hi,lo), B:[N,K] k-contig.
//   3-term: Ah*Bh + Ah*Bl + Al*Bh, fp32 accumulate.
// Block tile 256(M) x 128(N), BK=64, 2-stage cp.async pipeline, 256 thr
// (8 warps = 4m x 2n, warp tile 64x64). OUT=0: split bf16 out; OUT=1: fp32 out.
// Smem per stage: A 64KB + B 32KB. Rows of 128B (64 bf16, k-contig),
// 16B chunks XOR-swizzled: chunk c at (c ^ (row & 7)).
// ---------------------------------------------------------------------------
#define TM 256
#define TN 128
#define BKK 64
#define AH_OFF 0
#define AL_OFF 32768
#define BH_OFF 65536
#define BL_OFF 81920
#define STAGE_BYTES 98304
#define GEMM_SMEM  (2 * STAGE_BYTES)     // 192 KB

template<int OUT>
__global__ void __launch_bounds__(256, 1)
gemm_hmma(const __nv_bfloat16* __restrict__ Ah, const __nv_bfloat16* __restrict__ Al,
          int lda, size_t bsA,
          const __nv_bfloat16* __restrict__ Bh, const __nv_bfloat16* __restrict__ Bl,
          int ldb, size_t bsB,
          void* __restrict__ Coh, void* __restrict__ Col,
          int ldc, size_t bsC,
          const float* __restrict__ bias, float alpha, int K)
{
    extern __shared__ char smem[];
    const uint32_t sbase = smem_u32(smem);

    Ah += (size_t)blockIdx.z * bsA;  Al += (size_t)blockIdx.z * bsA;
    Bh += (size_t)blockIdx.z * bsB;  Bl += (size_t)blockIdx.z * bsB;

    const int tid  = threadIdx.x;
    const int lane = tid & 31;
    const int warp = tid >> 5;
    const int wm   = warp >> 1;           // 4 warps in m (64 rows each)
    const int wn   = warp & 1;            // 2 warps in n (64 cols each)
    const int m0   = blockIdx.y * TM;
    const int n0   = blockIdx.x * TN;

    // ---- loader: A row = tid (256 rows, 8 chunks hi + 8 lo);
    //              B row = tid>>1 (128 rows, 4 chunks each of hi & lo)
    const __nv_bfloat16* aSrcH = Ah + (size_t)(m0 + tid) * lda;
    const __nv_bfloat16* aSrcL = Al + (size_t)(m0 + tid) * lda;
    const int brow = tid >> 1;
    const __nv_bfloat16* bSrcH = Bh + (size_t)(n0 + brow) * ldb;
    const __nv_bfloat16* bSrcL = Bl + (size_t)(n0 + brow) * ldb;
    const uint32_t aRowOff = (uint32_t)tid * 128;
    const uint32_t bRowOff = (uint32_t)brow * 128;

    auto load_stage = [&](int s, int kt) {
        const uint32_t st = sbase + (uint32_t)s * STAGE_BYTES;
        const int ke = kt * BKK;
        #pragma unroll
        for (int c = 0; c < 8; c++) {
            const uint32_t sw = (uint32_t)((c ^ (tid & 7)) << 4);
            CP_ASYNC16(st + AH_OFF + aRowOff + sw, aSrcH + ke + c * 8);
            CP_ASYNC16(st + AL_OFF + aRowOff + sw, aSrcL + ke + c * 8);
        }
        #pragma unroll
        for (int j = 0; j < 4; j++) {
            const int c = (tid & 1) * 4 + j;
            const uint32_t sw = (uint32_t)((c ^ (brow & 7)) << 4);
            CP_ASYNC16(st + BH_OFF + bRowOff + sw, bSrcH + ke + c * 8);
            CP_ASYNC16(st + BL_OFF + bRowOff + sw, bSrcL + ke + c * 8);
        }
    };

    // ---- ldmatrix address precompute (same tile mapping validated in R7)
    const int g  = lane >> 3;             // 0..3
    const int r8 = lane & 7;
    uint32_t a_ro[4]; int a_sw[4];
    #pragma unroll
    for (int mf = 0; mf < 4; mf++) {
        const int row = wm * 64 + mf * 16 + ((g & 1) << 3) + r8;
        a_ro[mf] = AH_OFF + (uint32_t)row * 128;
        a_sw[mf] = row & 7;
    }
    const int a_ch = g >> 1;              // k16 half for A
    uint32_t b_ro[4]; int b_sw[4];
    #pragma unroll
    for (int nf = 0; nf < 4; nf++) {
        const int row = wn * 64 + nf * 16 + ((g >> 1) << 3) + r8;
        b_ro[nf] = BH_OFF + (uint32_t)row * 128;
        b_sw[nf] = row & 7;
    }
    const int b_ch = g & 1;               // k16 half for B

    float acc[4][8][4];
    #pragma unroll
    for (int i = 0; i < 4; i++)
        #pragma unroll
        for (int j = 0; j < 8; j++)
            #pragma unroll
            for (int k = 0; k < 4; k++) acc[i][j][k] = 0.f;

    const int nK = K / BKK;
    load_stage(0, 0); CP_COMMIT();

    for (int kt = 0; kt < nK; kt++) {
        const int s = kt & 1;
        if (kt + 1 < nK) load_stage(s ^ 1, kt + 1);
        CP_COMMIT();
        CP_WAIT1();
        __syncthreads();

        const uint32_t sa = sbase + (uint32_t)s * STAGE_BYTES;
        #pragma unroll
        for (int kk = 0; kk < 4; kk++) {
            uint32_t ahf[4][4], alf[4][4];
            #pragma unroll
            for (int mf = 0; mf < 4; mf++) {
                const uint32_t ch = (uint32_t)(((kk * 2 + a_ch) ^ a_sw[mf]) << 4);
                ldsm4(ahf[mf], sa + a_ro[mf] + ch);
                ldsm4(alf[mf], sa + a_ro[mf] + 32768u + ch);
            }
            #pragma unroll
            for (int nf = 0; nf < 4; nf++) {
                uint32_t bhf[4], blf[4];
                const uint32_t ch = (uint32_t)(((kk * 2 + b_ch) ^ b_sw[nf]) << 4);
                ldsm4(bhf, sa + b_ro[nf] + ch);
                ldsm4(blf, sa + b_ro[nf] + 16384u + ch);
                #pragma unroll
                for (int half = 0; half < 2; half++) {
                    const uint32_t* bh = &bhf[half * 2];
                    const uint32_t* bl = &blf[half * 2];
                    #pragma unroll
                    for (int mf = 0; mf < 4; mf++) {
                        float* a = acc[mf][nf * 2 + half];
                        mma_bf16(a, ahf[mf], bh[0], bh[1]);  // hi*hi
                        mma_bf16(a, ahf[mf], bl[0], bl[1]);  // hi*lo
                        mma_bf16(a, alf[mf], bh[0], bh[1]);  // lo*hi
                    }
                }
            }
        }
        __syncthreads();   // stage s free for next overwrite
    }

    // ---- epilogue
    const int mr = lane >> 2;
    const int nc = (lane & 3) * 2;
    #pragma unroll
    for (int mf = 0; mf < 4; mf++) {
        #pragma unroll
        for (int nf = 0; nf < 8; nf++) {
            const int m = m0 + wm * 64 + mf * 16 + mr;
            const int n = n0 + wn * 64 + nf * 8 + nc;
            float b0 = 0.f, b1 = 0.f;
            if (bias) { b0 = bias[n]; b1 = bias[n + 1]; }
            const float v0 = alpha * acc[mf][nf][0] + b0;
            const float v1 = alpha * acc[mf][nf][1] + b1;
            const float v2 = alpha * acc[mf][nf][2] + b0;
            const float v3 = alpha * acc[mf][nf][3] + b1;
            if (OUT == 1) {
                float* C = (float*)Coh + (size_t)blockIdx.z * bsC;
                *(float2*)&C[(size_t)m * ldc + n]       = make_float2(v0, v1);
                *(float2*)&C[(size_t)(m + 8) * ldc + n] = make_float2(v2, v3);
            } else {
                __nv_bfloat16* Ch = (__nv_bfloat16*)Coh + (size_t)blockIdx.z * bsC;
                __nv_bfloat16* Cl = (__nv_bfloat16*)Col + (size_t)blockIdx.z * bsC;
                split_store2(Ch, Cl, (size_t)m * ldc + n, v0, v1);
                split_store2(Ch, Cl, (size_t)(m + 8) * ldc + n, v2, v3);
            }
        }
    }
}

// ---------------------------------------------------------------------------
// Elementwise fp32 -> (hi, lo) bf16 split.
// ---------------------------------------------------------------------------
__global__ void __launch_bounds__(256)
split_f32(const float4* __restrict__ in, __nv_bfloat162* __restrict__ oh,
          __nv_bfloat162* __restrict__ ol, int n4)
{
    const int i = blockIdx.x * 256 + threadIdx.x;
    if (i >= n4) return;
    const float4 v = in[i];
    __nv_bfloat162 h01 = __floats2bfloat162_rn(v.x, v.y);
    __nv_bfloat162 h23 = __floats2bfloat162_rn(v.z, v.w);
    float2 f01 = __bfloat1622float2(h01);
    float2 f23 = __bfloat1622float2(h23);
    oh[2 * i]     = h01;
    oh[2 * i + 1] = h23;
    ol[2 * i]     = __floats2bfloat162_rn(v.x - f01.x, v.y - f01.y);
    ol[2 * i + 1] = __floats2bfloat162_rn(v.z - f23.x, v.w - f23.y);
}

// ---------------------------------------------------------------------------
// Transpose + split: in fp32 [R][C] (batch stride bsIn) -> out bf16 hi/lo [C][R].
// Block (32,8), 32x32 tiles.
// ---------------------------------------------------------------------------
__global__ void __launch_bounds__(256)
transpose_split(const float* __restrict__ in,
                __nv_bfloat16* __restrict__ oh, __nv_bfloat16* __restrict__ ol,
                int R, int C, size_t bsIn, size_t bsOut)
{
    __shared__ float tile[32][33];
    in += (size_t)blockIdx.z * bsIn;
    oh += (size_t)blockIdx.z * bsOut;
    ol += (size_t)blockIdx.z * bsOut;

    const int tx = threadIdx.x, ty = threadIdx.y;
    const int x  = blockIdx.x * 32 + tx;       // col in input
    const int y0 = blockIdx.y * 32;
    #pragma unroll
    for (int j = 0; j < 4; j++)
        tile[ty + j * 8][tx] = in[(size_t)(y0 + ty + j * 8) * C + x];
    __syncthreads();
    #pragma unroll
    for (int j = 0; j < 4; j++) {
        const float v = tile[tx][ty + j * 8];  // = in[y0+tx][bx*32+ty+j*8]
        const __nv_bfloat16 h = __float2bfloat16(v);
        const __nv_bfloat16 l = __float2bfloat16(v - __bfloat162float(h));
        const size_t o = (size_t)(blockIdx.x * 32 + ty + j * 8) * R + y0 + tx;
        oh[o] = h;
        ol[o] = l;
    }
}

// ---------------------------------------------------------------------------
// Softmax over split-bf16 rows (in place): reconstruct hi+lo, softmax fp32,
// write back split. 16384 rows of 2048; 1 block (256 thr) per row.
// ---------------------------------------------------------------------------
__global__ void __launch_bounds__(256)
softmax_split(__nv_bfloat16* __restrict__ Sh, __nv_bfloat16* __restrict__ Sl)
{
    const size_t base = (size_t)blockIdx.x * SEQ;
    __nv_bfloat162* ph = (__nv_bfloat162*)(Sh + base);
    __nv_bfloat162* pl = (__nv_bfloat162*)(Sl + base);
    const int t = threadIdx.x;

    float v[8];
    float m = -1e30f;
    #pragma unroll
    for (int i = 0; i < 4; i++) {
        const float2 hf = __bfloat1622float2(ph[t + i * 256]);
        const float2 lf = __bfloat1622float2(pl[t + i * 256]);
        v[2 * i]     = hf.x + lf.x;
        v[2 * i + 1] = hf.y + lf.y;
        m = fmaxf(m, fmaxf(v[2 * i], v[2 * i + 1]));
    }

    __shared__ float red[8];
    #pragma unroll
    for (int o = 16; o > 0; o >>= 1)
        m = fmaxf(m, __shfl_xor_sync(0xffffffffu, m, o));
    if ((t & 31) == 0) red[t >> 5] = m;
    __syncthreads();
    float mr = red[0];
    #pragma unroll
    for (int i = 1; i < 8; i++) mr = fmaxf(mr, red[i]);
    __syncthreads();

    float sum = 0.f;
    #pragma unroll
    for (int i = 0; i < 8; i++) {
        v[i] = __expf(v[i] - mr);
        sum += v[i];
    }
    #pragma unroll
    for (int o = 16; o > 0; o >>= 1)
        sum += __shfl_xor_sync(0xffffffffu, sum, o);
    if ((t & 31) == 0) red[t >> 5] = sum;
    __syncthreads();
    float sr = 0.f;
    #pragma unroll
    for (int i = 0; i < 8; i++) sr += red[i];
    const float inv = 1.0f / sr;

    #pragma unroll
    for (int i = 0; i < 4; i++) {
        const float p0 = v[2 * i] * inv;
        const float p1 = v[2 * i + 1] * inv;
        const __nv_bfloat162 h = __floats2bfloat162_rn(p0, p1);
        const float2 hf = __bfloat1622float2(h);
        ph[t + i * 256] = h;
        pl[t + i * 256] = __floats2bfloat162_rn(p0 - hf.x, p1 - hf.y);
    }
}

// ---------------------------------------------------------------------------
// Launch.  Inputs: x, Wq, bq, Wk, bk, Wv, bv, Wo, bo.  Output fp32 (8,2048,768)
// ---------------------------------------------------------------------------
extern "C" void kernel_launch(void* const* d_in, const int* in_sizes, int n_in,
                              void* d_out, int out_size)
{
    const float* x  = (const float*)d_in[0];
    const float* Wq = (const float*)d_in[1];
    const float* bq = (const float*)d_in[2];
    const float* Wk = (const float*)d_in[3];
    const float* bk = (const float*)d_in[4];
    const float* Wv = (const float*)d_in[5];
    const float* bv = (const float*)d_in[6];
    const float* Wo = (const float*)d_in[7];
    const float* bo = (const float*)d_in[8];
    float* out = (float*)d_out;

    __nv_bfloat16 *xh, *xl, *Wqh, *Wql, *Wkh, *Wkl, *Wvh, *Wvl, *Woh, *Wol;
    __nv_bfloat16 *Qh, *Ql, *Kh, *Kl, *Vth, *Vtl, *Sh, *Sl, *Oh, *Ol;
    float* V;
    cudaGetSymbolAddress((void**)&xh,  g_xh);  cudaGetSymbolAddress((void**)&xl,  g_xl);
    cudaGetSymbolAddress((void**)&Wqh, g_Wqh); cudaGetSymbolAddress((void**)&Wql, g_Wql);
    cudaGetSymbolAddress((void**)&Wkh, g_Wkh); cudaGetSymbolAddress((void**)&Wkl, g_Wkl);
    cudaGetSymbolAddress((void**)&Wvh, g_Wvh); cudaGetSymbolAddress((void**)&Wvl, g_Wvl);
    cudaGetSymbolAddress((void**)&Woh, g_Woh); cudaGetSymbolAddress((void**)&Wol, g_Wol);
    cudaGetSymbolAddress((void**)&Qh,  g_Qh);  cudaGetSymbolAddress((void**)&Ql,  g_Ql);
    cudaGetSymbolAddress((void**)&Kh,  g_Kh);  cudaGetSymbolAddress((void**)&Kl,  g_Kl);
    cudaGetSymbolAddress((void**)&V,   g_V);
    cudaGetSymbolAddress((void**)&Vth, g_Vth); cudaGetSymbolAddress((void**)&Vtl, g_Vtl);
    cudaGetSymbolAddress((void**)&Sh,  g_Sh);  cudaGetSymbolAddress((void**)&Sl,  g_Sl);
    cudaGetSymbolAddress((void**)&Oh,  g_Oh);  cudaGetSymbolAddress((void**)&Ol,  g_Ol);

    cudaFuncSetAttribute(gemm_hmma<0>, cudaFuncAttributeMaxDynamicSharedMemorySize, GEMM_SMEM);
    cudaFuncSetAttribute(gemm_hmma<1>, cudaFuncAttributeMaxDynamicSharedMemorySize, GEMM_SMEM);

    const float scale = 1.0f / sqrtf((float)EMB);
    const dim3 tb(32, 8);

    // 0) split x; transpose+split weights (W[e][f] -> Wt[f][e])
    split_f32<<<(ROWS * EMB / 4 + 255) / 256, 256>>>(
        (const float4*)x, (__nv_bfloat162*)xh, (__nv_bfloat162*)xl, ROWS * EMB / 4);
    {
        dim3 g(EMB / 32, EMB / 32, 1);
        transpose_split<<<g, tb>>>(Wq, Wqh, Wql, EMB, EMB, 0, 0);
        transpose_split<<<g, tb>>>(Wk, Wkh, Wkl, EMB, EMB, 0, 0);
        transpose_split<<<g, tb>>>(Wv, Wvh, Wvl, EMB, EMB, 0, 0);
        transpose_split<<<g, tb>>>(Wo, Woh, Wol, EMB, EMB, 0, 0);
    }

    // 1) QKV projections (M=16384, N=768, K=768). Q,K -> split; V -> fp32.
    {
        dim3 g(EMB / TN, ROWS / TM, 1);
        gemm_hmma<0><<<g, 256, GEMM_SMEM>>>(xh, xl, EMB, 0, Wqh, Wql, EMB, 0,
                                            Qh, Ql, EMB, 0, bq, 1.0f, EMB);
        gemm_hmma<0><<<g, 256, GEMM_SMEM>>>(xh, xl, EMB, 0, Wkh, Wkl, EMB, 0,
                                            Kh, Kl, EMB, 0, bk, 1.0f, EMB);
        gemm_hmma<1><<<g, 256, GEMM_SMEM>>>(xh, xl, EMB, 0, Wvh, Wvl, EMB, 0,
                                            V, nullptr, EMB, 0, bv, 1.0f, EMB);
    }

    // 2) V transpose+split per batch: [s][e] -> [e][s]
    {
        dim3 g(EMB / 32, SEQ / 32, BATCH);
        transpose_split<<<g, tb>>>(V, Vth, Vtl, SEQ, EMB,
                                   (size_t)SEQ * EMB, (size_t)SEQ * EMB);
    }

    // 3) Scores: S = scale * Q * K^T per batch -> split bf16
    {
        dim3 g(SEQ / TN, SEQ / TM, BATCH);
        gemm_hmma<0><<<g, 256, GEMM_SMEM>>>(Qh, Ql, EMB, (size_t)SEQ * EMB,
                                            Kh, Kl, EMB, (size_t)SEQ * EMB,
                                            Sh, Sl, SEQ, (size_t)SEQ * SEQ,
                                            nullptr, scale, EMB);
    }

    // 4) Softmax (in place on split S)
    softmax_split<<<ROWS, 256>>>(Sh, Sl);

    // 5) O = P * V per batch (A = S [q][s], B = Vt [e][s]) -> split bf16
    {
        dim3 g(EMB / TN, SEQ / TM, BATCH);
        gemm_hmma<0><<<g, 256, GEMM_SMEM>>>(Sh, Sl, SEQ, (size_t)SEQ * SEQ,
                                            Vth, Vtl, SEQ, (size_t)EMB * SEQ,
                                            Oh, Ol, EMB, (size_t)SEQ * EMB,
                                            nullptr, 1.0f, SEQ);
    }

    // 6) Output projection -> d_out (fp32)
    {
        dim3 g(EMB / TN, ROWS / TM, 1);
        gemm_hmma<1><<<g, 256, GEMM_SMEM>>>(Oh, Ol, EMB, 0, Woh, Wol, EMB, 0,
                                            out, nullptr, EMB, 0, bo, 1.0f, EMB);
    }
}

// round 9
// speedup vs baseline: 2.3839x; 1.0018x over previous
#include <cuda_runtime.h>
#include <cuda_bf16.h>
#include <math.h>
#include <stdint.h>

// Problem shape (fixed by reference): B=8, N=2048, E=768
#define BATCH 8
#define SEQ   2048
#define EMB   768
#define ROWS  (BATCH * SEQ)          // 16384

// ---------------------------------------------------------------------------
// Scratch (__device__ globals; no allocations allowed).
// All GEMM operands live as split bf16 (hi, lo) pairs, k-contiguous.
// ---------------------------------------------------------------------------
__device__ __align__(256) __nv_bfloat16 g_xh[ROWS * EMB], g_xl[ROWS * EMB];
__device__ __align__(256) __nv_bfloat16 g_Wqh[EMB * EMB], g_Wql[EMB * EMB];
__device__ __align__(256) __nv_bfloat16 g_Wkh[EMB * EMB], g_Wkl[EMB * EMB];
__device__ __align__(256) __nv_bfloat16 g_Wvh[EMB * EMB], g_Wvl[EMB * EMB];
__device__ __align__(256) __nv_bfloat16 g_Woh[EMB * EMB], g_Wol[EMB * EMB];
__device__ __align__(256) __nv_bfloat16 g_Qh[ROWS * EMB], g_Ql[ROWS * EMB];
__device__ __align__(256) __nv_bfloat16 g_Kh[ROWS * EMB], g_Kl[ROWS * EMB];
__device__ __align__(256) float         g_V [ROWS * EMB];
__device__ __align__(256) __nv_bfloat16 g_Vth[ROWS * EMB], g_Vtl[ROWS * EMB]; // [b][e][s]
__device__ __align__(256) __nv_bfloat16 g_Sh[(size_t)BATCH * SEQ * SEQ];
__device__ __align__(256) __nv_bfloat16 g_Sl[(size_t)BATCH * SEQ * SEQ];
__device__ __align__(256) __nv_bfloat16 g_Oh[ROWS * EMB], g_Ol[ROWS * EMB];

// ---------------------------------------------------------------------------
// Helpers
// ---------------------------------------------------------------------------
__device__ __forceinline__ uint32_t smem_u32(const void* p) {
    uint32_t a;
    asm("{ .reg .u64 t; cvta.to.shared.u64 t, %1; cvt.u32.u64 %0, t; }"
        : "=r"(a) : "l"(p));
    return a;
}

__device__ __forceinline__ void ldsm4(uint32_t* r, uint32_t addr) {
    asm volatile("ldmatrix.sync.aligned.m8n8.x4.shared.b16 {%0,%1,%2,%3}, [%4];"
                 : "=r"(r[0]), "=r"(r[1]), "=r"(r[2]), "=r"(r[3]) : "r"(addr));
}

__device__ __forceinline__ void mma_bf16(float* c, const uint32_t* a,
                                         uint32_t b0, uint32_t b1)
{
    asm volatile(
        "mma.sync.aligned.m16n8k16.row.col.f32.bf16.bf16.f32 "
        "{%0,%1,%2,%3}, {%4,%5,%6,%7}, {%8,%9}, {%0,%1,%2,%3};"
        : "+f"(c[0]), "+f"(c[1]), "+f"(c[2]), "+f"(c[3])
        : "r"(a[0]), "r"(a[1]), "r"(a[2]), "r"(a[3]), "r"(b0), "r"(b1));
}

#define CP_ASYNC16(dst, src) \
    asm volatile("cp.async.cg.shared.global [%0], [%1], 16;" :: "r"(dst), "l"(src))
#define CP_COMMIT() asm volatile("cp.async.commit_group;" ::: "memory")
#define CP_WAIT1()  asm volatile("cp.async.wait_group 1;"  ::: "memory")

__device__ __forceinline__ void split_store2(__nv_bfloat16* Ch, __nv_bfloat16* Cl,
                                             size_t idx, float v0, float v1)
{
    __nv_bfloat162 h = __floats2bfloat162_rn(v0, v1);
    float2 hf = __bfloat1622float2(h);
    __nv_bfloat162 l = __floats2bfloat162_rn(v0 - hf.x, v1 - hf.y);
    *(__nv_bfloat162*)(Ch + idx) = h;
    *(__nv_bfloat162*)(Cl + idx) = l;
}

// ---------------------------------------------------------------------------
// HMMA split-bf16 GEMM.
//   C[M,N] = alpha * A * B^T (+ bias), A:[M,K] k-contig (hi,lo), B:[N,K] k-contig.
//   3-term: Ah*Bh + Ah*Bl + Al*Bh, fp32 accumulate.
// Block tile 256(M) x 128(N), BK=64, 2-stage cp.async pipeline, 256 thr
// (8 warps = 4m x 2n, warp tile 64x64). OUT=0: split bf16 out; OUT=1: fp32 out.
// Mainloop is TERM-MAJOR: all hi*hi mmas, then hi*lo, then lo*hi — same-acc
// reuse distance 32 mmas (vs 1 in R8) to kill accumulator RAW stalls.
// ---------------------------------------------------------------------------
#define TM 256
#define TN 128
#define BKK 64
#define AH_OFF 0
#define AL_OFF 32768
#define BH_OFF 65536
#define BL_OFF 81920
#define STAGE_BYTES 98304
#define GEMM_SMEM  (2 * STAGE_BYTES)     // 192 KB

template<int OUT>
__global__ void __launch_bounds__(256, 1)
gemm_hmma(const __nv_bfloat16* __restrict__ Ah, const __nv_bfloat16* __restrict__ Al,
          int lda, size_t bsA,
          const __nv_bfloat16* __restrict__ Bh, const __nv_bfloat16* __restrict__ Bl,
          int ldb, size_t bsB,
          void* __restrict__ Coh, void* __restrict__ Col,
          int ldc, size_t bsC,
          const float* __restrict__ bias, float alpha, int K)
{
    extern __shared__ char smem[];
    const uint32_t sbase = smem_u32(smem);

    Ah += (size_t)blockIdx.z * bsA;  Al += (size_t)blockIdx.z * bsA;
    Bh += (size_t)blockIdx.z * bsB;  Bl += (size_t)blockIdx.z * bsB;

    const int tid  = threadIdx.x;
    const int lane = tid & 31;
    const int warp = tid >> 5;
    const int wm   = warp >> 1;           // 4 warps in m (64 rows each)
    const int wn   = warp & 1;            // 2 warps in n (64 cols each)
    const int m0   = blockIdx.y * TM;
    const int n0   = blockIdx.x * TN;

    // ---- loader: A row = tid (256 rows, 8 chunks hi + 8 lo);
    //              B row = tid>>1 (128 rows, 4 chunks each of hi & lo)
    const __nv_bfloat16* aSrcH = Ah + (size_t)(m0 + tid) * lda;
    const __nv_bfloat16* aSrcL = Al + (size_t)(m0 + tid) * lda;
    const int brow = tid >> 1;
    const __nv_bfloat16* bSrcH = Bh + (size_t)(n0 + brow) * ldb;
    const __nv_bfloat16* bSrcL = Bl + (size_t)(n0 + brow) * ldb;
    const uint32_t aRowOff = (uint32_t)tid * 128;
    const uint32_t bRowOff = (uint32_t)brow * 128;

    auto load_stage = [&](int s, int kt) {
        const uint32_t st = sbase + (uint32_t)s * STAGE_BYTES;
        const int ke = kt * BKK;
        #pragma unroll
        for (int c = 0; c < 8; c++) {
            const uint32_t sw = (uint32_t)((c ^ (tid & 7)) << 4);
            CP_ASYNC16(st + AH_OFF + aRowOff + sw, aSrcH + ke + c * 8);
            CP_ASYNC16(st + AL_OFF + aRowOff + sw, aSrcL + ke + c * 8);
        }
        #pragma unroll
        for (int j = 0; j < 4; j++) {
            const int c = (tid & 1) * 4 + j;
            const uint32_t sw = (uint32_t)((c ^ (brow & 7)) << 4);
            CP_ASYNC16(st + BH_OFF + bRowOff + sw, bSrcH + ke + c * 8);
            CP_ASYNC16(st + BL_OFF + bRowOff + sw, bSrcL + ke + c * 8);
        }
    };

    // ---- ldmatrix address precompute (same tile mapping validated in R7/R8)
    const int g  = lane >> 3;             // 0..3
    const int r8 = lane & 7;
    uint32_t a_ro[4]; int a_sw[4];
    #pragma unroll
    for (int mf = 0; mf < 4; mf++) {
        const int row = wm * 64 + mf * 16 + ((g & 1) << 3) + r8;
        a_ro[mf] = AH_OFF + (uint32_t)row * 128;
        a_sw[mf] = row & 7;
    }
    const int a_ch = g >> 1;              // k16 half for A
    uint32_t b_ro[4]; int b_sw[4];
    #pragma unroll
    for (int nf = 0; nf < 4; nf++) {
        const int row = wn * 64 + nf * 16 + ((g >> 1) << 3) + r8;
        b_ro[nf] = BH_OFF + (uint32_t)row * 128;
        b_sw[nf] = row & 7;
    }
    const int b_ch = g & 1;               // k16 half for B

    float acc[4][8][4];
    #pragma unroll
    for (int i = 0; i < 4; i++)
        #pragma unroll
        for (int j = 0; j < 8; j++)
            #pragma unroll
            for (int k = 0; k < 4; k++) acc[i][j][k] = 0.f;

    const int nK = K / BKK;
    load_stage(0, 0); CP_COMMIT();

    for (int kt = 0; kt < nK; kt++) {
        const int s = kt & 1;
        if (kt + 1 < nK) load_stage(s ^ 1, kt + 1);
        CP_COMMIT();
        CP_WAIT1();
        __syncthreads();

        const uint32_t sa = sbase + (uint32_t)s * STAGE_BYTES;
        #pragma unroll
        for (int kk = 0; kk < 4; kk++) {
            // ---- load ALL fragments for this k16 step first
            uint32_t ahf[4][4], alf[4][4], bhf[4][4], blf[4][4];
            #pragma unroll
            for (int mf = 0; mf < 4; mf++) {
                const uint32_t ch = (uint32_t)(((kk * 2 + a_ch) ^ a_sw[mf]) << 4);
                ldsm4(ahf[mf], sa + a_ro[mf] + ch);
                ldsm4(alf[mf], sa + a_ro[mf] + 32768u + ch);
            }
            #pragma unroll
            for (int nf = 0; nf < 4; nf++) {
                const uint32_t ch = (uint32_t)(((kk * 2 + b_ch) ^ b_sw[nf]) << 4);
                ldsm4(bhf[nf], sa + b_ro[nf] + ch);
                ldsm4(blf[nf], sa + b_ro[nf] + 16384u + ch);
            }
            // ---- term-major mma issue: 32 independent mmas per term
            #pragma unroll
            for (int mf = 0; mf < 4; mf++)            // hi * hi
                #pragma unroll
                for (int nf = 0; nf < 4; nf++)
                    #pragma unroll
                    for (int half = 0; half < 2; half++)
                        mma_bf16(acc[mf][nf * 2 + half], ahf[mf],
                                 bhf[nf][half * 2], bhf[nf][half * 2 + 1]);
            #pragma unroll
            for (int mf = 0; mf < 4; mf++)            // hi * lo
                #pragma unroll
                for (int nf = 0; nf < 4; nf++)
                    #pragma unroll
                    for (int half = 0; half < 2; half++)
                        mma_bf16(acc[mf][nf * 2 + half], ahf[mf],
                                 blf[nf][half * 2], blf[nf][half * 2 + 1]);
            #pragma unroll
            for (int mf = 0; mf < 4; mf++)            // lo * hi
                #pragma unroll
                for (int nf = 0; nf < 4; nf++)
                    #pragma unroll
                    for (int half = 0; half < 2; half++)
                        mma_bf16(acc[mf][nf * 2 + half], alf[mf],
                                 bhf[nf][half * 2], bhf[nf][half * 2 + 1]);
        }
        __syncthreads();   // stage s free for next overwrite
    }

    // ---- epilogue
    const int mr = lane >> 2;
    const int nc = (lane & 3) * 2;
    #pragma unroll
    for (int mf = 0; mf < 4; mf++) {
        #pragma unroll
        for (int nf = 0; nf < 8; nf++) {
            const int m = m0 + wm * 64 + mf * 16 + mr;
            const int n = n0 + wn * 64 + nf * 8 + nc;
            float b0 = 0.f, b1 = 0.f;
            if (bias) { b0 = bias[n]; b1 = bias[n + 1]; }
            const float v0 = alpha * acc[mf][nf][0] + b0;
            const float v1 = alpha * acc[mf][nf][1] + b1;
            const float v2 = alpha * acc[mf][nf][2] + b0;
            const float v3 = alpha * acc[mf][nf][3] + b1;
            if (OUT == 1) {
                float* C = (float*)Coh + (size_t)blockIdx.z * bsC;
                *(float2*)&C[(size_t)m * ldc + n]       = make_float2(v0, v1);
                *(float2*)&C[(size_t)(m + 8) * ldc + n] = make_float2(v2, v3);
            } else {
                __nv_bfloat16* Ch = (__nv_bfloat16*)Coh + (size_t)blockIdx.z * bsC;
                __nv_bfloat16* Cl = (__nv_bfloat16*)Col + (size_t)blockIdx.z * bsC;
                split_store2(Ch, Cl, (size_t)m * ldc + n, v0, v1);
                split_store2(Ch, Cl, (size_t)(m + 8) * ldc + n, v2, v3);
            }
        }
    }
}

// ---------------------------------------------------------------------------
// Elementwise fp32 -> (hi, lo) bf16 split.
// ---------------------------------------------------------------------------
__global__ void __launch_bounds__(256)
split_f32(const float4* __restrict__ in, __nv_bfloat162* __restrict__ oh,
          __nv_bfloat162* __restrict__ ol, int n4)
{
    const int i = blockIdx.x * 256 + threadIdx.x;
    if (i >= n4) return;
    const float4 v = in[i];
    __nv_bfloat162 h01 = __floats2bfloat162_rn(v.x, v.y);
    __nv_bfloat162 h23 = __floats2bfloat162_rn(v.z, v.w);
    float2 f01 = __bfloat1622float2(h01);
    float2 f23 = __bfloat1622float2(h23);
    oh[2 * i]     = h01;
    oh[2 * i + 1] = h23;
    ol[2 * i]     = __floats2bfloat162_rn(v.x - f01.x, v.y - f01.y);
    ol[2 * i + 1] = __floats2bfloat162_rn(v.z - f23.x, v.w - f23.y);
}

// ---------------------------------------------------------------------------
// Transpose + split: in fp32 [R][C] (batch stride bsIn) -> out bf16 hi/lo [C][R].
// Block (32,8), 32x32 tiles.
// ---------------------------------------------------------------------------
__global__ void __launch_bounds__(256)
transpose_split(const float* __restrict__ in,
                __nv_bfloat16* __restrict__ oh, __nv_bfloat16* __restrict__ ol,
                int R, int C, size_t bsIn, size_t bsOut)
{
    __shared__ float tile[32][33];
    in += (size_t)blockIdx.z * bsIn;
    oh += (size_t)blockIdx.z * bsOut;
    ol += (size_t)blockIdx.z * bsOut;

    const int tx = threadIdx.x, ty = threadIdx.y;
    const int x  = blockIdx.x * 32 + tx;       // col in input
    const int y0 = blockIdx.y * 32;
    #pragma unroll
    for (int j = 0; j < 4; j++)
        tile[ty + j * 8][tx] = in[(size_t)(y0 + ty + j * 8) * C + x];
    __syncthreads();
    #pragma unroll
    for (int j = 0; j < 4; j++) {
        const float v = tile[tx][ty + j * 8];  // = in[y0+tx][bx*32+ty+j*8]
        const __nv_bfloat16 h = __float2bfloat16(v);
        const __nv_bfloat16 l = __float2bfloat16(v - __bfloat162float(h));
        const size_t o = (size_t)(blockIdx.x * 32 + ty + j * 8) * R + y0 + tx;
        oh[o] = h;
        ol[o] = l;
    }
}

// ---------------------------------------------------------------------------
// Softmax over split-bf16 rows (in place): reconstruct hi+lo, softmax fp32,
// write back split. 16384 rows of 2048; 1 block (256 thr) per row.
// ---------------------------------------------------------------------------
__global__ void __launch_bounds__(256)
softmax_split(__nv_bfloat16* __restrict__ Sh, __nv_bfloat16* __restrict__ Sl)
{
    const size_t base = (size_t)blockIdx.x * SEQ;
    __nv_bfloat162* ph = (__nv_bfloat162*)(Sh + base);
    __nv_bfloat162* pl = (__nv_bfloat162*)(Sl + base);
    const int t = threadIdx.x;

    float v[8];
    float m = -1e30f;
    #pragma unroll
    for (int i = 0; i < 4; i++) {
        const float2 hf = __bfloat1622float2(ph[t + i * 256]);
        const float2 lf = __bfloat1622float2(pl[t + i * 256]);
        v[2 * i]     = hf.x + lf.x;
        v[2 * i + 1] = hf.y + lf.y;
        m = fmaxf(m, fmaxf(v[2 * i], v[2 * i + 1]));
    }

    __shared__ float red[8];
    #pragma unroll
    for (int o = 16; o > 0; o >>= 1)
        m = fmaxf(m, __shfl_xor_sync(0xffffffffu, m, o));
    if ((t & 31) == 0) red[t >> 5] = m;
    __syncthreads();
    float mr = red[0];
    #pragma unroll
    for (int i = 1; i < 8; i++) mr = fmaxf(mr, red[i]);
    __syncthreads();

    float sum = 0.f;
    #pragma unroll
    for (int i = 0; i < 8; i++) {
        v[i] = __expf(v[i] - mr);
        sum += v[i];
    }
    #pragma unroll
    for (int o = 16; o > 0; o >>= 1)
        sum += __shfl_xor_sync(0xffffffffu, sum, o);
    if ((t & 31) == 0) red[t >> 5] = sum;
    __syncthreads();
    float sr = 0.f;
    #pragma unroll
    for (int i = 0; i < 8; i++) sr += red[i];
    const float inv = 1.0f / sr;

    #pragma unroll
    for (int i = 0; i < 4; i++) {
        const float p0 = v[2 * i] * inv;
        const float p1 = v[2 * i + 1] * inv;
        const __nv_bfloat162 h = __floats2bfloat162_rn(p0, p1);
        const float2 hf = __bfloat1622float2(h);
        ph[t + i * 256] = h;
        pl[t + i * 256] = __floats2bfloat162_rn(p0 - hf.x, p1 - hf.y);
    }
}

// ---------------------------------------------------------------------------
// Launch.  Inputs: x, Wq, bq, Wk, bk, Wv, bv, Wo, bo.  Output fp32 (8,2048,768)
// ---------------------------------------------------------------------------
extern "C" void kernel_launch(void* const* d_in, const int* in_sizes, int n_in,
                              void* d_out, int out_size)
{
    const float* x  = (const float*)d_in[0];
    const float* Wq = (const float*)d_in[1];
    const float* bq = (const float*)d_in[2];
    const float* Wk = (const float*)d_in[3];
    const float* bk = (const float*)d_in[4];
    const float* Wv = (const float*)d_in[5];
    const float* bv = (const float*)d_in[6];
    const float* Wo = (const float*)d_in[7];
    const float* bo = (const float*)d_in[8];
    float* out = (float*)d_out;

    __nv_bfloat16 *xh, *xl, *Wqh, *Wql, *Wkh, *Wkl, *Wvh, *Wvl, *Woh, *Wol;
    __nv_bfloat16 *Qh, *Ql, *Kh, *Kl, *Vth, *Vtl, *Sh, *Sl, *Oh, *Ol;
    float* V;
    cudaGetSymbolAddress((void**)&xh,  g_xh);  cudaGetSymbolAddress((void**)&xl,  g_xl);
    cudaGetSymbolAddress((void**)&Wqh, g_Wqh); cudaGetSymbolAddress((void**)&Wql, g_Wql);
    cudaGetSymbolAddress((void**)&Wkh, g_Wkh); cudaGetSymbolAddress((void**)&Wkl, g_Wkl);
    cudaGetSymbolAddress((void**)&Wvh, g_Wvh); cudaGetSymbolAddress((void**)&Wvl, g_Wvl);
    cudaGetSymbolAddress((void**)&Woh, g_Woh); cudaGetSymbolAddress((void**)&Wol, g_Wol);
    cudaGetSymbolAddress((void**)&Qh,  g_Qh);  cudaGetSymbolAddress((void**)&Ql,  g_Ql);
    cudaGetSymbolAddress((void**)&Kh,  g_Kh);  cudaGetSymbolAddress((void**)&Kl,  g_Kl);
    cudaGetSymbolAddress((void**)&V,   g_V);
    cudaGetSymbolAddress((void**)&Vth, g_Vth); cudaGetSymbolAddress((void**)&Vtl, g_Vtl);
    cudaGetSymbolAddress((void**)&Sh,  g_Sh);  cudaGetSymbolAddress((void**)&Sl,  g_Sl);
    cudaGetSymbolAddress((void**)&Oh,  g_Oh);  cudaGetSymbolAddress((void**)&Ol,  g_Ol);

    cudaFuncSetAttribute(gemm_hmma<0>, cudaFuncAttributeMaxDynamicSharedMemorySize, GEMM_SMEM);
    cudaFuncSetAttribute(gemm_hmma<1>, cudaFuncAttributeMaxDynamicSharedMemorySize, GEMM_SMEM);

    const float scale = 1.0f / sqrtf((float)EMB);
    const dim3 tb(32, 8);

    // 0) split x; transpose+split weights (W[e][f] -> Wt[f][e])
    split_f32<<<(ROWS * EMB / 4 + 255) / 256, 256>>>(
        (const float4*)x, (__nv_bfloat162*)xh, (__nv_bfloat162*)xl, ROWS * EMB / 4);
    {
        dim3 g(EMB / 32, EMB / 32, 1);
        transpose_split<<<g, tb>>>(Wq, Wqh, Wql, EMB, EMB, 0, 0);
        transpose_split<<<g, tb>>>(Wk, Wkh, Wkl, EMB, EMB, 0, 0);
        transpose_split<<<g, tb>>>(Wv, Wvh, Wvl, EMB, EMB, 0, 0);
        transpose_split<<<g, tb>>>(Wo, Woh, Wol, EMB, EMB, 0, 0);
    }

    // 1) QKV projections (M=16384, N=768, K=768). Q,K -> split; V -> fp32.
    {
        dim3 g(EMB / TN, ROWS / TM, 1);
        gemm_hmma<0><<<g, 256, GEMM_SMEM>>>(xh, xl, EMB, 0, Wqh, Wql, EMB, 0,
                                            Qh, Ql, EMB, 0, bq, 1.0f, EMB);
        gemm_hmma<0><<<g, 256, GEMM_SMEM>>>(xh, xl, EMB, 0, Wkh, Wkl, EMB, 0,
                                            Kh, Kl, EMB, 0, bk, 1.0f, EMB);
        gemm_hmma<1><<<g, 256, GEMM_SMEM>>>(xh, xl, EMB, 0, Wvh, Wvl, EMB, 0,
                                            V, nullptr, EMB, 0, bv, 1.0f, EMB);
    }

    // 2) V transpose+split per batch: [s][e] -> [e][s]
    {
        dim3 g(EMB / 32, SEQ / 32, BATCH);
        transpose_split<<<g, tb>>>(V, Vth, Vtl, SEQ, EMB,
                                   (size_t)SEQ * EMB, (size_t)SEQ * EMB);
    }

    // 3) Scores: S = scale * Q * K^T per batch -> split bf16
    {
        dim3 g(SEQ / TN, SEQ / TM, BATCH);
        gemm_hmma<0><<<g, 256, GEMM_SMEM>>>(Qh, Ql, EMB, (size_t)SEQ * EMB,
                                            Kh, Kl, EMB, (size_t)SEQ * EMB,
                                            Sh, Sl, SEQ, (size_t)SEQ * SEQ,
                                            nullptr, scale, EMB);
    }

    // 4) Softmax (in place on split S)
    softmax_split<<<ROWS, 256>>>(Sh, Sl);

    // 5) O = P * V per batch (A = S [q][s], B = Vt [e][s]) -> split bf16
    {
        dim3 g(EMB / TN, SEQ / TM, BATCH);
        gemm_hmma<0><<<g, 256, GEMM_SMEM>>>(Sh, Sl, SEQ, (size_t)SEQ * SEQ,
                                            Vth, Vtl, SEQ, (size_t)EMB * SEQ,
                                            Oh, Ol, EMB, (size_t)SEQ * EMB,
                                            nullptr, 1.0f, SEQ);
    }

    // 6) Output projection -> d_out (fp32)
    {
        dim3 g(EMB / TN, ROWS / TM, 1);
        gemm_hmma<1><<<g, 256, GEMM_SMEM>>>(Oh, Ol, EMB, 0, Woh, Wol, EMB, 0,
                                            out, nullptr, EMB, 0, bo, 1.0f, EMB);
    }
}